// round 15
// baseline (speedup 1.0000x reference)
#include <cuda_runtime.h>
#include <cuda_fp16.h>
#include <math.h>
#include <stdint.h>

// Problem dims (fixed by reference)
#define NB 4
#define SEQ 2048
#define EMB 1024
#define NH 16
#define HD 64
#define FF 4096
#define MROWS (NB * SEQ)          // 8192
#define X_SIZE (NB * SEQ * EMB)   // 8388608

// ---------------- scratch (device globals; no allocation allowed) ----------
__device__ __half g_xn [MROWS * EMB];
__device__ __half g_q  [MROWS * EMB];
__device__ __half g_k  [MROWS * EMB];
__device__ __half g_v  [MROWS * EMB];
__device__ __half g_att[MROWS * EMB];
__device__ float  g_x1 [MROWS * EMB];
__device__ __half g_xn2[MROWS * EMB];
__device__ __half g_ffn[MROWS * FF];
// transposed fp16 weights [N][K]
__device__ __half g_wtq[EMB * EMB];
__device__ __half g_wtk[EMB * EMB];
__device__ __half g_wtv[EMB * EMB];
__device__ __half g_wto[EMB * EMB];
__device__ __half g_wt1[FF * EMB];
__device__ __half g_wt2[EMB * FF];

// ---------------- helpers ---------------------------------------------------
__device__ __forceinline__ uint32_t h2u(__half2 h) {
    return *reinterpret_cast<uint32_t*>(&h);
}
__device__ __forceinline__ uint32_t pack_h2(float lo, float hi) {
    return h2u(__floats2half2_rn(lo, hi));
}

__device__ __forceinline__ uint32_t s2u(const void* p) {
    uint32_t a;
    asm("{ .reg .u64 t; cvta.to.shared.u64 t, %1; cvt.u32.u64 %0, t; }"
        : "=r"(a) : "l"(p));
    return a;
}

__device__ __forceinline__ void cp16(uint32_t dst, const void* src) {
    asm volatile("cp.async.cg.shared.global [%0], [%1], 16;"
                 :: "r"(dst), "l"(src));
}
#define CP_COMMIT() asm volatile("cp.async.commit_group;" ::: "memory")
#define CP_WAIT1()  asm volatile("cp.async.wait_group 1;" ::: "memory")

__device__ __forceinline__ void ldm_x4(uint32_t r[4], uint32_t addr) {
    asm volatile("ldmatrix.sync.aligned.m8n8.x4.shared.b16 {%0,%1,%2,%3}, [%4];"
                 : "=r"(r[0]), "=r"(r[1]), "=r"(r[2]), "=r"(r[3])
                 : "r"(addr));
}
__device__ __forceinline__ void ldm_x4_t(uint32_t r[4], uint32_t addr) {
    asm volatile("ldmatrix.sync.aligned.m8n8.x4.trans.shared.b16 {%0,%1,%2,%3}, [%4];"
                 : "=r"(r[0]), "=r"(r[1]), "=r"(r[2]), "=r"(r[3])
                 : "r"(addr));
}

__device__ __forceinline__ void mma_f16(float d[4], const uint32_t a[4],
                                        const uint32_t b0, const uint32_t b1) {
    asm volatile(
        "mma.sync.aligned.m16n8k16.row.col.f32.f16.f16.f32 "
        "{%0,%1,%2,%3},{%4,%5,%6,%7},{%8,%9},{%0,%1,%2,%3};"
        : "+f"(d[0]), "+f"(d[1]), "+f"(d[2]), "+f"(d[3])
        : "r"(a[0]), "r"(a[1]), "r"(a[2]), "r"(a[3]), "r"(b0), "r"(b1));
}

// typed pair-store (fp32 or fp16 destination)
__device__ __forceinline__ void store2(float* p, float a, float b) {
    *reinterpret_cast<float2*>(p) = make_float2(a, b);
}
__device__ __forceinline__ void store2(__half* p, float a, float b) {
    *reinterpret_cast<uint32_t*>(p) = pack_h2(a, b);
}

// ---------------- weight transpose + fp16 convert ---------------------------
__global__ __launch_bounds__(256) void transpose4_h_kernel(
    const float* __restrict__ w0, const float* __restrict__ w1,
    const float* __restrict__ w2, const float* __restrict__ w3,
    __half* __restrict__ o0, __half* __restrict__ o1,
    __half* __restrict__ o2, __half* __restrict__ o3)
{
    const int z = blockIdx.z;
    const float* in = (z == 0) ? w0 : (z == 1) ? w1 : (z == 2) ? w2 : w3;
    __half* out     = (z == 0) ? o0 : (z == 1) ? o1 : (z == 2) ? o2 : o3;
    __shared__ float t[32][33];
    const int bc = blockIdx.x * 32, br = blockIdx.y * 32;
    const int x = threadIdx.x, y0 = threadIdx.y;
#pragma unroll
    for (int y = y0; y < 32; y += 8)
        t[y][x] = in[(size_t)(br + y) * EMB + bc + x];
    __syncthreads();
#pragma unroll
    for (int y = y0; y < 32; y += 8)
        out[(size_t)(bc + y) * EMB + br + x] = __float2half(t[x][y]);
}

__global__ __launch_bounds__(256) void transpose_h_kernel(
    const float* __restrict__ in, __half* __restrict__ out, int R, int C)
{
    __shared__ float t[32][33];
    const int bc = blockIdx.x * 32, br = blockIdx.y * 32;
    const int x = threadIdx.x, y0 = threadIdx.y;
#pragma unroll
    for (int y = y0; y < 32; y += 8)
        t[y][x] = in[(size_t)(br + y) * C + bc + x];
    __syncthreads();
#pragma unroll
    for (int y = y0; y < 32; y += 8)
        out[(size_t)(bc + y) * R + br + x] = __float2half(t[x][y]);
}

// ---------------- layernorm (fp32 in, fp16 out) -----------------------------
__global__ __launch_bounds__(256) void ln_kernel(
    const float* __restrict__ in, const float* __restrict__ g,
    const float* __restrict__ b, __half* __restrict__ out)
{
    const int row = blockIdx.x;
    const float* xr = in + (size_t)row * EMB;
    __half* orow = out + (size_t)row * EMB;
    const int tid = threadIdx.x;

    float vals[4];
    float s = 0.f, sq = 0.f;
#pragma unroll
    for (int i = 0; i < 4; i++) {
        float v = xr[i * 256 + tid];
        vals[i] = v; s += v; sq += v * v;
    }
    __shared__ float red[16];
#pragma unroll
    for (int off = 16; off; off >>= 1) {
        s  += __shfl_xor_sync(0xffffffffu, s,  off);
        sq += __shfl_xor_sync(0xffffffffu, sq, off);
    }
    const int warp = tid >> 5, lane = tid & 31;
    if (lane == 0) { red[warp] = s; red[warp + 8] = sq; }
    __syncthreads();
    if (warp == 0) {
        float ss = (lane < 8) ? red[lane] : 0.f;
        float qq = (lane < 8) ? red[lane + 8] : 0.f;
#pragma unroll
        for (int off = 4; off; off >>= 1) {
            ss += __shfl_xor_sync(0xffffffffu, ss, off);
            qq += __shfl_xor_sync(0xffffffffu, qq, off);
        }
        if (lane == 0) { red[0] = ss; red[1] = qq; }
    }
    __syncthreads();
    const float mean = red[0] * (1.0f / EMB);
    const float var  = red[1] * (1.0f / EMB) - mean * mean;
    const float inv  = rsqrtf(var + 1e-5f);
#pragma unroll
    for (int i = 0; i < 4; i++) {
        int idx = i * 256 + tid;
        orow[idx] = __float2half((vals[i] - mean) * inv * g[idx] + b[idx]);
    }
}

// ---------------- fp16 tensor-core GEMM (256x128 tile, BK=32, 3-stage) ------
// C[M,N] = act(A[M,K] @ BT[N,K]^T + bias [+ res]).
// Block tile 256x128, 256 thr (8 warps: 4 row-groups x 2 col-groups),
// warp tile 64x64. Smem row pitch 40 halves (80B, conflict-free ldmatrix).
#define PITCH 40
#define A_STG_H (256 * PITCH)        // halves per A stage (10240)
#define B_STG_H (128 * PITCH)        // halves per B stage (5120)
#define A_STG_B (A_STG_H * 2)        // bytes (20480)
#define B_STG_B (B_STG_H * 2)        // bytes (10240)
#define NSTAGE 3
#define GEMM_DSMEM (NSTAGE * (A_STG_B + B_STG_B))   // 92160 bytes

template <typename TOut, bool RELU, bool RES>
__device__ __forceinline__ void gemm_h_body(
    const __half* __restrict__ A, const __half* __restrict__ BT,
    const float* __restrict__ bias, const float* __restrict__ res,
    TOut* __restrict__ C, int M, int N, int K, int bx, int by)
{
    extern __shared__ __half dsm[];
    __half* sA = dsm;                        // 3 x A_STG_H
    __half* sB = dsm + NSTAGE * A_STG_H;     // 3 x B_STG_H

    const int tid = threadIdx.x;
    const int warpId = tid >> 5, lane = tid & 31;
    const int t = lane & 3, g = lane >> 2;
    const int wr = warpId & 3;               // 0..3 : 64-row group
    const int wc = warpId >> 2;              // 0..1 : 64-col group
    const int rowStart = by * 256;
    const int colStart = bx * 128;
    const int KT = K / 32;

    // stage-loader mapping: 16B chunks. A: 4/thread, B: 2/thread.
    // chunk u: row = u>>2, col8 = (u&3)*8
    const __half* ApG[4];
    uint32_t sAo[4];
#pragma unroll
    for (int it = 0; it < 4; it++) {
        const int u = tid + it * 256;
        const int row = u >> 2, c8 = (u & 3) * 8;
        ApG[it] = A + (size_t)(rowStart + row) * K + c8;
        sAo[it] = s2u(sA) + (uint32_t)((row * PITCH + c8) * 2);
    }
    const __half* BpG[2];
    uint32_t sBo[2];
#pragma unroll
    for (int it = 0; it < 2; it++) {
        const int u = tid + it * 256;
        const int row = u >> 2, c8 = (u & 3) * 8;
        BpG[it] = BT + (size_t)(colStart + row) * K + c8;
        sBo[it] = s2u(sB) + (uint32_t)((row * PITCH + c8) * 2);
    }

    // ldmatrix base addresses (per-lane)
    const uint32_t aBase = s2u(sA) +
        (uint32_t)((wr * 64 + (lane & 15)) * (PITCH * 2) + (lane >> 4) * 16);
    const uint32_t bBase = s2u(sB) +
        (uint32_t)((wc * 64 + ((lane >> 4) << 3) + (lane & 7)) * (PITCH * 2) +
                   ((lane >> 3) & 1) * 16);

    float acc[4][8][4];
#pragma unroll
    for (int mt = 0; mt < 4; mt++)
#pragma unroll
        for (int nt = 0; nt < 8; nt++)
#pragma unroll
            for (int r = 0; r < 4; r++) acc[mt][nt][r] = 0.f;

    // prologue: issue stages 0 and 1
#pragma unroll
    for (int st = 0; st < 2; st++) {
#pragma unroll
        for (int it = 0; it < 4; it++)
            cp16(sAo[it] + st * A_STG_B, ApG[it] + st * 32);
#pragma unroll
        for (int it = 0; it < 2; it++)
            cp16(sBo[it] + st * B_STG_B, BpG[it] + st * 32);
        CP_COMMIT();
    }

    int buf = 0;
    for (int kt = 0; kt < KT; kt++) {
        CP_WAIT1();            // stage kt landed
        __syncthreads();       // visible to all; also orders prev compute

        // issue stage kt+2 into buffer (kt+2)%3 (compute on it ended iter kt-1)
        if (kt + 2 < KT) {
            const int nb = (buf + 2 >= NSTAGE) ? buf + 2 - NSTAGE : buf + 2;
            const int ko = (kt + 2) * 32;
#pragma unroll
            for (int it = 0; it < 4; it++)
                cp16(sAo[it] + nb * A_STG_B, ApG[it] + ko);
#pragma unroll
            for (int it = 0; it < 2; it++)
                cp16(sBo[it] + nb * B_STG_B, BpG[it] + ko);
        }
        CP_COMMIT();           // keep group count in lockstep

        // ---- compute: two k16 sub-steps on buf ----
        const uint32_t aOff = aBase + buf * A_STG_B;
        const uint32_t bOff = bBase + buf * B_STG_B;
#pragma unroll
        for (int ks = 0; ks < 2; ks++) {
            uint32_t af[4][4];
#pragma unroll
            for (int mt = 0; mt < 4; mt++)
                ldm_x4(af[mt], aOff + ks * 32 + mt * (16 * PITCH * 2));
            uint32_t bf[4][4];
#pragma unroll
            for (int jb = 0; jb < 4; jb++)
                ldm_x4(bf[jb], bOff + ks * 32 + jb * (16 * PITCH * 2));
#pragma unroll
            for (int mt = 0; mt < 4; mt++)
#pragma unroll
                for (int jb = 0; jb < 4; jb++) {
                    mma_f16(acc[mt][2 * jb],     af[mt], bf[jb][0], bf[jb][1]);
                    mma_f16(acc[mt][2 * jb + 1], af[mt], bf[jb][2], bf[jb][3]);
                }
        }
        buf = (buf + 1 >= NSTAGE) ? 0 : buf + 1;
    }

    // ---- epilogue ----
#pragma unroll
    for (int mt = 0; mt < 4; mt++) {
        const int r0 = rowStart + wr * 64 + mt * 16 + g;
#pragma unroll
        for (int nt = 0; nt < 8; nt++) {
            const int c0 = colStart + wc * 64 + nt * 8 + t * 2;
            float bx0 = bias[c0], by0 = bias[c0 + 1];
            float v0 = acc[mt][nt][0] + bx0;
            float v1 = acc[mt][nt][1] + by0;
            float v2 = acc[mt][nt][2] + bx0;
            float v3 = acc[mt][nt][3] + by0;
            const size_t off0 = (size_t)r0 * N + c0;
            const size_t off1 = (size_t)(r0 + 8) * N + c0;
            if (RES) {
                float2 q0 = *reinterpret_cast<const float2*>(&res[off0]);
                float2 q1 = *reinterpret_cast<const float2*>(&res[off1]);
                v0 += q0.x; v1 += q0.y; v2 += q1.x; v3 += q1.y;
            }
            if (RELU) {
                v0 = fmaxf(v0, 0.f); v1 = fmaxf(v1, 0.f);
                v2 = fmaxf(v2, 0.f); v3 = fmaxf(v3, 0.f);
            }
            store2(&C[off0], v0, v1);
            store2(&C[off1], v2, v3);
        }
    }
}

template <typename TOut, bool RELU, bool RES>
__global__ __launch_bounds__(256, 1) void gemm_h_kernel(
    const __half* __restrict__ A, const __half* __restrict__ BT,
    const float* __restrict__ bias, const float* __restrict__ res,
    TOut* __restrict__ C, int M, int N, int K)
{
    gemm_h_body<TOut, RELU, RES>(A, BT, bias, res, C, M, N, K,
                                 blockIdx.x, blockIdx.y);
}

__global__ __launch_bounds__(256, 1) void gemm_h_qkv_kernel(
    const __half* __restrict__ A,
    const __half* __restrict__ wt0, const __half* __restrict__ wt1,
    const __half* __restrict__ wt2,
    const float* __restrict__ b0, const float* __restrict__ b1,
    const float* __restrict__ b2,
    __half* __restrict__ c0, __half* __restrict__ c1, __half* __restrict__ c2)
{
    const int z = blockIdx.z;
    const __half* BT  = (z == 0) ? wt0 : (z == 1) ? wt1 : wt2;
    const float* bias = (z == 0) ? b0  : (z == 1) ? b1  : b2;
    __half* C         = (z == 0) ? c0  : (z == 1) ? c1  : c2;
    gemm_h_body<__half, false, false>(A, BT, bias, nullptr, C,
                                      MROWS, EMB, EMB, blockIdx.x, blockIdx.y);
}

// ---------------- flash attention (fp16 m16n8k16) ---------------------------
#define AP 72

__global__ __launch_bounds__(128) void attn_h_kernel(
    const __half* __restrict__ q, const __half* __restrict__ k,
    const __half* __restrict__ v, __half* __restrict__ out)
{
    __shared__ __half Ks[64 * AP];
    __shared__ __half Vs[64 * AP];
    __shared__ __half Ps[64 * AP];

    const int qt = blockIdx.x, h = blockIdx.y, n = blockIdx.z;
    const int tid = threadIdx.x;
    const int warp = tid >> 5, lane = tid & 31;
    const int g = lane >> 2, t = lane & 3;
    const int w16 = warp * 16;
    const size_t base = ((size_t)n * SEQ) * EMB + h * HD;

    const uint32_t ksB = s2u(Ks), vsB = s2u(Vs), psB = s2u(Ps);

#pragma unroll
    for (int it = 0; it < 4; it++) {
        const int u = tid + it * 128;
        const int rr = u >> 3, c8 = (u & 7) * 8;
        *reinterpret_cast<uint4*>(&Ks[rr * AP + c8]) =
            *reinterpret_cast<const uint4*>(
                &q[base + (size_t)(qt * 64 + rr) * EMB + c8]);
    }
    __syncthreads();

    uint32_t qf[4][4];
#pragma unroll
    for (int ks = 0; ks < 4; ks++)
        ldm_x4(qf[ks], ksB + (uint32_t)(((w16 + (lane & 15)) * AP +
                                         ks * 16 + ((lane >> 4) * 8)) * 2));

    float m0 = -INFINITY, m1 = -INFINITY, l0 = 0.f, l1 = 0.f;
    float o[8][4];
#pragma unroll
    for (int nt = 0; nt < 8; nt++)
#pragma unroll
        for (int r = 0; r < 4; r++) o[nt][r] = 0.f;

    for (int kt = 0; kt < SEQ / 64; kt++) {
        __syncthreads();
#pragma unroll
        for (int it = 0; it < 4; it++) {
            const int u = tid + it * 128;
            const int rr = u >> 3, c8 = (u & 7) * 8;
            const size_t gsrc = base + (size_t)(kt * 64 + rr) * EMB + c8;
            *reinterpret_cast<uint4*>(&Ks[rr * AP + c8]) =
                *reinterpret_cast<const uint4*>(&k[gsrc]);
            *reinterpret_cast<uint4*>(&Vs[rr * AP + c8]) =
                *reinterpret_cast<const uint4*>(&v[gsrc]);
        }
        __syncthreads();

        float s[8][4];
#pragma unroll
        for (int nt = 0; nt < 8; nt++)
#pragma unroll
            for (int r = 0; r < 4; r++) s[nt][r] = 0.f;

#pragma unroll
        for (int ks = 0; ks < 4; ks++) {
#pragma unroll
            for (int j = 0; j < 4; j++) {
                uint32_t bf[4];
                ldm_x4(bf, ksB + (uint32_t)(((j * 16 + ((lane >> 4) << 3) +
                                              (lane & 7)) * AP + ks * 16 +
                                             ((lane >> 3) & 1) * 8) * 2));
                mma_f16(s[2 * j],     qf[ks], bf[0], bf[1]);
                mma_f16(s[2 * j + 1], qf[ks], bf[2], bf[3]);
            }
        }

#pragma unroll
        for (int nt = 0; nt < 8; nt++)
#pragma unroll
            for (int r = 0; r < 4; r++) s[nt][r] *= 0.125f;

        float mt0 = -INFINITY, mt1 = -INFINITY;
#pragma unroll
        for (int nt = 0; nt < 8; nt++) {
            mt0 = fmaxf(mt0, fmaxf(s[nt][0], s[nt][1]));
            mt1 = fmaxf(mt1, fmaxf(s[nt][2], s[nt][3]));
        }
        mt0 = fmaxf(mt0, __shfl_xor_sync(0xffffffffu, mt0, 1));
        mt0 = fmaxf(mt0, __shfl_xor_sync(0xffffffffu, mt0, 2));
        mt1 = fmaxf(mt1, __shfl_xor_sync(0xffffffffu, mt1, 1));
        mt1 = fmaxf(mt1, __shfl_xor_sync(0xffffffffu, mt1, 2));

        const float mn0 = fmaxf(m0, mt0), mn1 = fmaxf(m1, mt1);
        const float c0 = __expf(m0 - mn0), c1 = __expf(m1 - mn1);
        float ls0 = 0.f, ls1 = 0.f;
#pragma unroll
        for (int nt = 0; nt < 8; nt++) {
            const float p0 = __expf(s[nt][0] - mn0);
            const float p1 = __expf(s[nt][1] - mn0);
            const float p2 = __expf(s[nt][2] - mn1);
            const float p3 = __expf(s[nt][3] - mn1);
            ls0 += p0 + p1; ls1 += p2 + p3;
            *reinterpret_cast<uint32_t*>(
                &Ps[(w16 + g) * AP + nt * 8 + t * 2]) = pack_h2(p0, p1);
            *reinterpret_cast<uint32_t*>(
                &Ps[(w16 + g + 8) * AP + nt * 8 + t * 2]) = pack_h2(p2, p3);
        }
        ls0 += __shfl_xor_sync(0xffffffffu, ls0, 1);
        ls0 += __shfl_xor_sync(0xffffffffu, ls0, 2);
        ls1 += __shfl_xor_sync(0xffffffffu, ls1, 1);
        ls1 += __shfl_xor_sync(0xffffffffu, ls1, 2);
        l0 = l0 * c0 + ls0; l1 = l1 * c1 + ls1;
        m0 = mn0; m1 = mn1;
#pragma unroll
        for (int nt = 0; nt < 8; nt++) {
            o[nt][0] *= c0; o[nt][1] *= c0;
            o[nt][2] *= c1; o[nt][3] *= c1;
        }
        __syncwarp();

#pragma unroll
        for (int ks = 0; ks < 4; ks++) {
            uint32_t pf[4];
            ldm_x4(pf, psB + (uint32_t)(((w16 + (lane & 15)) * AP + ks * 16 +
                                         ((lane >> 4) * 8)) * 2));
#pragma unroll
            for (int j = 0; j < 4; j++) {
                uint32_t vf[4];
                const int row = ks * 16 + (lane & 7) + ((lane >> 3) & 1) * 8;
                ldm_x4_t(vf, vsB + (uint32_t)((row * AP + j * 16 +
                                               (lane >> 4) * 8) * 2));
                mma_f16(o[2 * j],     pf, vf[0], vf[1]);
                mma_f16(o[2 * j + 1], pf, vf[2], vf[3]);
            }
        }
    }

    const float i0 = 1.f / l0, i1 = 1.f / l1;
    const size_t row0 = base + (size_t)(qt * 64 + w16 + g) * EMB;
    const size_t row1 = base + (size_t)(qt * 64 + w16 + g + 8) * EMB;
#pragma unroll
    for (int nt = 0; nt < 8; nt++) {
        const int c = nt * 8 + t * 2;
        *reinterpret_cast<uint32_t*>(&out[row0 + c]) =
            pack_h2(o[nt][0] * i0, o[nt][1] * i0);
        *reinterpret_cast<uint32_t*>(&out[row1 + c]) =
            pack_h2(o[nt][2] * i1, o[nt][3] * i1);
    }
}

// ---------------- logits + GAN loss -----------------------------------------
__global__ void loss_kernel(const float* __restrict__ xfin,
                            const float* __restrict__ wlr,
                            const float* __restrict__ blr,
                            float* __restrict__ out)
{
    __shared__ float slog[4];
    const int warp = threadIdx.x >> 5, lane = threadIdx.x & 31;
    if (warp < 4) {
        const float* xr = xfin + (size_t)warp * SEQ * EMB;  // token 0
        float s = 0.f;
        for (int i = lane; i < EMB; i += 32) s = fmaf(xr[i], wlr[i], s);
#pragma unroll
        for (int off = 16; off; off >>= 1)
            s += __shfl_xor_sync(0xffffffffu, s, off);
        if (lane == 0) slog[warp] = s + blr[0];
    }
    __syncthreads();
    if (threadIdx.x == 0) {
        auto sp = [](float t) {
            return fmaxf(t, 0.f) + log1pf(expf(-fabsf(t)));
        };
        float loss_real = 0.5f * (sp(-slog[0]) + sp(-slog[1]));
        float loss_fake = 0.5f * (sp( slog[2]) + sp( slog[3]));
        out[0] = 0.5f * (loss_fake + loss_real);
        out[1] = loss_fake;
    }
}

// ---------------- launch ----------------------------------------------------
extern "C" void kernel_launch(void* const* d_in, const int* in_sizes, int n_in,
                              void* d_out, int out_size)
{
    const float* x     = (const float*)d_in[0];
    const float* wq    = (const float*)d_in[1];
    const float* bq    = (const float*)d_in[2];
    const float* wk    = (const float*)d_in[3];
    const float* bk    = (const float*)d_in[4];
    const float* wv    = (const float*)d_in[5];
    const float* bv    = (const float*)d_in[6];
    const float* wo    = (const float*)d_in[7];
    const float* bo    = (const float*)d_in[8];
    const float* ln1_g = (const float*)d_in[9];
    const float* ln1_b = (const float*)d_in[10];
    const float* ln2_g = (const float*)d_in[11];
    const float* ln2_b = (const float*)d_in[12];
    const float* w1    = (const float*)d_in[13];
    const float* b1    = (const float*)d_in[14];
    const float* w2    = (const float*)d_in[15];
    const float* b2    = (const float*)d_in[16];
    const float* wlr   = (const float*)d_in[17];
    const float* blr   = (const float*)d_in[18];
    float* out = (float*)d_out;

    __half *xn, *qh, *kh, *vh, *att, *xn2, *ffn;
    float* x1;
    __half *wtq, *wtk, *wtv, *wto, *wt1, *wt2;
    cudaGetSymbolAddress((void**)&xn,  g_xn);
    cudaGetSymbolAddress((void**)&qh,  g_q);
    cudaGetSymbolAddress((void**)&kh,  g_k);
    cudaGetSymbolAddress((void**)&vh,  g_v);
    cudaGetSymbolAddress((void**)&att, g_att);
    cudaGetSymbolAddress((void**)&x1,  g_x1);
    cudaGetSymbolAddress((void**)&xn2, g_xn2);
    cudaGetSymbolAddress((void**)&ffn, g_ffn);
    cudaGetSymbolAddress((void**)&wtq, g_wtq);
    cudaGetSymbolAddress((void**)&wtk, g_wtk);
    cudaGetSymbolAddress((void**)&wtv, g_wtv);
    cudaGetSymbolAddress((void**)&wto, g_wto);
    cudaGetSymbolAddress((void**)&wt1, g_wt1);
    cudaGetSymbolAddress((void**)&wt2, g_wt2);

    // raise dynamic smem limits
    cudaFuncSetAttribute(gemm_h_kernel<float, false, true>,
                         cudaFuncAttributeMaxDynamicSharedMemorySize, GEMM_DSMEM);
    cudaFuncSetAttribute(gemm_h_kernel<__half, true, false>,
                         cudaFuncAttributeMaxDynamicSharedMemorySize, GEMM_DSMEM);
    cudaFuncSetAttribute(gemm_h_qkv_kernel,
                         cudaFuncAttributeMaxDynamicSharedMemorySize, GEMM_DSMEM);

    // 0) weight transposes + fp16 convert
    dim3 tb(32, 8);
    transpose4_h_kernel<<<dim3(EMB / 32, EMB / 32, 4), tb>>>(
        wq, wk, wv, wo, wtq, wtk, wtv, wto);
    transpose_h_kernel<<<dim3(FF / 32,  EMB / 32), tb>>>(w1, wt1, EMB, FF);
    transpose_h_kernel<<<dim3(EMB / 32, FF / 32),  tb>>>(w2, wt2, FF, EMB);

    // 1) LN1 -> fp16
    ln_kernel<<<MROWS, 256>>>(x, ln1_g, ln1_b, xn);

    // 2) QKV projections -> fp16 q,k,v
    dim3 gQKV(EMB / 128, MROWS / 256, 3);
    gemm_h_qkv_kernel<<<gQKV, 256, GEMM_DSMEM>>>(xn, wtq, wtk, wtv,
                                                 bq, bk, bv, qh, kh, vh);

    // 3) attention (fp16 mma) -> fp16 att
    dim3 gAttn(SEQ / 64, NH, NB);
    attn_h_kernel<<<gAttn, 128>>>(qh, kh, vh, att);

    // 4) out-proj + residual(x fp32) -> x1 fp32
    dim3 gProj(EMB / 128, MROWS / 256);
    gemm_h_kernel<float, false, true><<<gProj, 256, GEMM_DSMEM>>>(
        att, wto, bo, x, x1, MROWS, EMB, EMB);

    // 5) LN2 -> fp16
    ln_kernel<<<MROWS, 256>>>(x1, ln2_g, ln2_b, xn2);

    // 6) FFN1 + ReLU -> fp16 ffn
    dim3 gFF1(FF / 128, MROWS / 256);
    gemm_h_kernel<__half, true, false><<<gFF1, 256, GEMM_DSMEM>>>(
        xn2, wt1, b1, nullptr, ffn, MROWS, FF, EMB);

    // 7) FFN2 + residual(x1 fp32) -> final fp32 out
    gemm_h_kernel<float, false, true><<<gProj, 256, GEMM_DSMEM>>>(
        ffn, wt2, b2, x1, out, MROWS, EMB, FF);

    // 8) logits + losses
    loss_kernel<<<1, 128>>>(out, wlr, blr, out + X_SIZE);
}

// round 16
// speedup vs baseline: 1.0031x; 1.0031x over previous
#include <cuda_runtime.h>
#include <cuda_fp16.h>
#include <math.h>
#include <stdint.h>

// Problem dims (fixed by reference)
#define NB 4
#define SEQ 2048
#define EMB 1024
#define NH 16
#define HD 64
#define FF 4096
#define MROWS (NB * SEQ)          // 8192
#define X_SIZE (NB * SEQ * EMB)   // 8388608

// ---------------- scratch (device globals; no allocation allowed) ----------
__device__ __half g_xn [MROWS * EMB];
__device__ __half g_q  [MROWS * EMB];
__device__ __half g_k  [MROWS * EMB];
__device__ __half g_v  [MROWS * EMB];
__device__ __half g_att[MROWS * EMB];
__device__ float  g_x1 [MROWS * EMB];
__device__ __half g_xn2[MROWS * EMB];
__device__ __half g_ffn[MROWS * FF];
// transposed fp16 weights [N][K]
__device__ __half g_wtq[EMB * EMB];
__device__ __half g_wtk[EMB * EMB];
__device__ __half g_wtv[EMB * EMB];
__device__ __half g_wto[EMB * EMB];
__device__ __half g_wt1[FF * EMB];
__device__ __half g_wt2[EMB * FF];

// ---------------- helpers ---------------------------------------------------
__device__ __forceinline__ uint32_t h2u(__half2 h) {
    return *reinterpret_cast<uint32_t*>(&h);
}
__device__ __forceinline__ uint32_t pack_h2(float lo, float hi) {
    return h2u(__floats2half2_rn(lo, hi));
}

__device__ __forceinline__ uint32_t s2u(const void* p) {
    uint32_t a;
    asm("{ .reg .u64 t; cvta.to.shared.u64 t, %1; cvt.u32.u64 %0, t; }"
        : "=r"(a) : "l"(p));
    return a;
}

__device__ __forceinline__ void cp16(uint32_t dst, const void* src) {
    asm volatile("cp.async.cg.shared.global [%0], [%1], 16;"
                 :: "r"(dst), "l"(src));
}
#define CP_COMMIT() asm volatile("cp.async.commit_group;" ::: "memory")
#define CP_WAIT1()  asm volatile("cp.async.wait_group 1;" ::: "memory")

__device__ __forceinline__ void ldm_x4(uint32_t r[4], uint32_t addr) {
    asm volatile("ldmatrix.sync.aligned.m8n8.x4.shared.b16 {%0,%1,%2,%3}, [%4];"
                 : "=r"(r[0]), "=r"(r[1]), "=r"(r[2]), "=r"(r[3])
                 : "r"(addr));
}
__device__ __forceinline__ void ldm_x4_t(uint32_t r[4], uint32_t addr) {
    asm volatile("ldmatrix.sync.aligned.m8n8.x4.trans.shared.b16 {%0,%1,%2,%3}, [%4];"
                 : "=r"(r[0]), "=r"(r[1]), "=r"(r[2]), "=r"(r[3])
                 : "r"(addr));
}

__device__ __forceinline__ void mma_f16(float d[4], const uint32_t a[4],
                                        const uint32_t b0, const uint32_t b1) {
    asm volatile(
        "mma.sync.aligned.m16n8k16.row.col.f32.f16.f16.f32 "
        "{%0,%1,%2,%3},{%4,%5,%6,%7},{%8,%9},{%0,%1,%2,%3};"
        : "+f"(d[0]), "+f"(d[1]), "+f"(d[2]), "+f"(d[3])
        : "r"(a[0]), "r"(a[1]), "r"(a[2]), "r"(a[3]), "r"(b0), "r"(b1));
}

// typed pair-store (fp32 or fp16 destination)
__device__ __forceinline__ void store2(float* p, float a, float b) {
    *reinterpret_cast<float2*>(p) = make_float2(a, b);
}
__device__ __forceinline__ void store2(__half* p, float a, float b) {
    *reinterpret_cast<uint32_t*>(p) = pack_h2(a, b);
}

// ---------------- weight transpose + fp16 convert ---------------------------
__global__ __launch_bounds__(256) void transpose4_h_kernel(
    const float* __restrict__ w0, const float* __restrict__ w1,
    const float* __restrict__ w2, const float* __restrict__ w3,
    __half* __restrict__ o0, __half* __restrict__ o1,
    __half* __restrict__ o2, __half* __restrict__ o3)
{
    const int z = blockIdx.z;
    const float* in = (z == 0) ? w0 : (z == 1) ? w1 : (z == 2) ? w2 : w3;
    __half* out     = (z == 0) ? o0 : (z == 1) ? o1 : (z == 2) ? o2 : o3;
    __shared__ float t[32][33];
    const int bc = blockIdx.x * 32, br = blockIdx.y * 32;
    const int x = threadIdx.x, y0 = threadIdx.y;
#pragma unroll
    for (int y = y0; y < 32; y += 8)
        t[y][x] = in[(size_t)(br + y) * EMB + bc + x];
    __syncthreads();
#pragma unroll
    for (int y = y0; y < 32; y += 8)
        out[(size_t)(bc + y) * EMB + br + x] = __float2half(t[x][y]);
}

__global__ __launch_bounds__(256) void transpose_h_kernel(
    const float* __restrict__ in, __half* __restrict__ out, int R, int C)
{
    __shared__ float t[32][33];
    const int bc = blockIdx.x * 32, br = blockIdx.y * 32;
    const int x = threadIdx.x, y0 = threadIdx.y;
#pragma unroll
    for (int y = y0; y < 32; y += 8)
        t[y][x] = in[(size_t)(br + y) * C + bc + x];
    __syncthreads();
#pragma unroll
    for (int y = y0; y < 32; y += 8)
        out[(size_t)(bc + y) * R + br + x] = __float2half(t[x][y]);
}

// ---------------- layernorm (fp32 in, fp16 out) -----------------------------
__global__ __launch_bounds__(256) void ln_kernel(
    const float* __restrict__ in, const float* __restrict__ g,
    const float* __restrict__ b, __half* __restrict__ out)
{
    const int row = blockIdx.x;
    const float* xr = in + (size_t)row * EMB;
    __half* orow = out + (size_t)row * EMB;
    const int tid = threadIdx.x;

    float vals[4];
    float s = 0.f, sq = 0.f;
#pragma unroll
    for (int i = 0; i < 4; i++) {
        float v = xr[i * 256 + tid];
        vals[i] = v; s += v; sq += v * v;
    }
    __shared__ float red[16];
#pragma unroll
    for (int off = 16; off; off >>= 1) {
        s  += __shfl_xor_sync(0xffffffffu, s,  off);
        sq += __shfl_xor_sync(0xffffffffu, sq, off);
    }
    const int warp = tid >> 5, lane = tid & 31;
    if (lane == 0) { red[warp] = s; red[warp + 8] = sq; }
    __syncthreads();
    if (warp == 0) {
        float ss = (lane < 8) ? red[lane] : 0.f;
        float qq = (lane < 8) ? red[lane + 8] : 0.f;
#pragma unroll
        for (int off = 4; off; off >>= 1) {
            ss += __shfl_xor_sync(0xffffffffu, ss, off);
            qq += __shfl_xor_sync(0xffffffffu, qq, off);
        }
        if (lane == 0) { red[0] = ss; red[1] = qq; }
    }
    __syncthreads();
    const float mean = red[0] * (1.0f / EMB);
    const float var  = red[1] * (1.0f / EMB) - mean * mean;
    const float inv  = rsqrtf(var + 1e-5f);
#pragma unroll
    for (int i = 0; i < 4; i++) {
        int idx = i * 256 + tid;
        orow[idx] = __float2half((vals[i] - mean) * inv * g[idx] + b[idx]);
    }
}

// ---------------- fp16 tensor-core GEMM (256x128 tile, BK=32, 3-stage) ------
// C[M,N] = act(A[M,K] @ BT[N,K]^T + bias [+ res]).
// Block tile 256x128, 256 thr (8 warps: 4 row-groups x 2 col-groups),
// warp tile 64x64. Smem row pitch 40 halves (80B, conflict-free ldmatrix).
#define PITCH 40
#define A_STG_H (256 * PITCH)        // halves per A stage (10240)
#define B_STG_H (128 * PITCH)        // halves per B stage (5120)
#define A_STG_B (A_STG_H * 2)        // bytes (20480)
#define B_STG_B (B_STG_H * 2)        // bytes (10240)
#define NSTAGE 3
#define GEMM_DSMEM (NSTAGE * (A_STG_B + B_STG_B))   // 92160 bytes

template <typename TOut, bool RELU, bool RES>
__device__ __forceinline__ void gemm_h_body(
    const __half* __restrict__ A, const __half* __restrict__ BT,
    const float* __restrict__ bias, const float* __restrict__ res,
    TOut* __restrict__ C, int M, int N, int K, int bx, int by)
{
    extern __shared__ __half dsm[];
    __half* sA = dsm;                        // 3 x A_STG_H
    __half* sB = dsm + NSTAGE * A_STG_H;     // 3 x B_STG_H

    const int tid = threadIdx.x;
    const int warpId = tid >> 5, lane = tid & 31;
    const int t = lane & 3, g = lane >> 2;
    const int wr = warpId & 3;               // 0..3 : 64-row group
    const int wc = warpId >> 2;              // 0..1 : 64-col group
    const int rowStart = by * 256;
    const int colStart = bx * 128;
    const int KT = K / 32;

    // stage-loader mapping: 16B chunks. A: 4/thread, B: 2/thread.
    // chunk u: row = u>>2, col8 = (u&3)*8
    const __half* ApG[4];
    uint32_t sAo[4];
#pragma unroll
    for (int it = 0; it < 4; it++) {
        const int u = tid + it * 256;
        const int row = u >> 2, c8 = (u & 3) * 8;
        ApG[it] = A + (size_t)(rowStart + row) * K + c8;
        sAo[it] = s2u(sA) + (uint32_t)((row * PITCH + c8) * 2);
    }
    const __half* BpG[2];
    uint32_t sBo[2];
#pragma unroll
    for (int it = 0; it < 2; it++) {
        const int u = tid + it * 256;
        const int row = u >> 2, c8 = (u & 3) * 8;
        BpG[it] = BT + (size_t)(colStart + row) * K + c8;
        sBo[it] = s2u(sB) + (uint32_t)((row * PITCH + c8) * 2);
    }

    // ldmatrix base addresses (per-lane)
    const uint32_t aBase = s2u(sA) +
        (uint32_t)((wr * 64 + (lane & 15)) * (PITCH * 2) + (lane >> 4) * 16);
    const uint32_t bBase = s2u(sB) +
        (uint32_t)((wc * 64 + ((lane >> 4) << 3) + (lane & 7)) * (PITCH * 2) +
                   ((lane >> 3) & 1) * 16);

    float acc[4][8][4];
#pragma unroll
    for (int mt = 0; mt < 4; mt++)
#pragma unroll
        for (int nt = 0; nt < 8; nt++)
#pragma unroll
            for (int r = 0; r < 4; r++) acc[mt][nt][r] = 0.f;

    // prologue: issue stages 0 and 1
#pragma unroll
    for (int st = 0; st < 2; st++) {
#pragma unroll
        for (int it = 0; it < 4; it++)
            cp16(sAo[it] + st * A_STG_B, ApG[it] + st * 32);
#pragma unroll
        for (int it = 0; it < 2; it++)
            cp16(sBo[it] + st * B_STG_B, BpG[it] + st * 32);
        CP_COMMIT();
    }

    int buf = 0;
    for (int kt = 0; kt < KT; kt++) {
        CP_WAIT1();            // stage kt landed
        __syncthreads();       // visible to all; also orders prev compute

        // issue stage kt+2 into buffer (kt+2)%3 (compute on it ended iter kt-1)
        if (kt + 2 < KT) {
            const int nb = (buf + 2 >= NSTAGE) ? buf + 2 - NSTAGE : buf + 2;
            const int ko = (kt + 2) * 32;
#pragma unroll
            for (int it = 0; it < 4; it++)
                cp16(sAo[it] + nb * A_STG_B, ApG[it] + ko);
#pragma unroll
            for (int it = 0; it < 2; it++)
                cp16(sBo[it] + nb * B_STG_B, BpG[it] + ko);
        }
        CP_COMMIT();           // keep group count in lockstep

        // ---- compute: two k16 sub-steps on buf ----
        const uint32_t aOff = aBase + buf * A_STG_B;
        const uint32_t bOff = bBase + buf * B_STG_B;
#pragma unroll
        for (int ks = 0; ks < 2; ks++) {
            uint32_t af[4][4];
#pragma unroll
            for (int mt = 0; mt < 4; mt++)
                ldm_x4(af[mt], aOff + ks * 32 + mt * (16 * PITCH * 2));
            uint32_t bf[4][4];
#pragma unroll
            for (int jb = 0; jb < 4; jb++)
                ldm_x4(bf[jb], bOff + ks * 32 + jb * (16 * PITCH * 2));
#pragma unroll
            for (int mt = 0; mt < 4; mt++)
#pragma unroll
                for (int jb = 0; jb < 4; jb++) {
                    mma_f16(acc[mt][2 * jb],     af[mt], bf[jb][0], bf[jb][1]);
                    mma_f16(acc[mt][2 * jb + 1], af[mt], bf[jb][2], bf[jb][3]);
                }
        }
        buf = (buf + 1 >= NSTAGE) ? 0 : buf + 1;
    }

    // ---- epilogue ----
#pragma unroll
    for (int mt = 0; mt < 4; mt++) {
        const int r0 = rowStart + wr * 64 + mt * 16 + g;
#pragma unroll
        for (int nt = 0; nt < 8; nt++) {
            const int c0 = colStart + wc * 64 + nt * 8 + t * 2;
            float bx0 = bias[c0], by0 = bias[c0 + 1];
            float v0 = acc[mt][nt][0] + bx0;
            float v1 = acc[mt][nt][1] + by0;
            float v2 = acc[mt][nt][2] + bx0;
            float v3 = acc[mt][nt][3] + by0;
            const size_t off0 = (size_t)r0 * N + c0;
            const size_t off1 = (size_t)(r0 + 8) * N + c0;
            if (RES) {
                float2 q0 = *reinterpret_cast<const float2*>(&res[off0]);
                float2 q1 = *reinterpret_cast<const float2*>(&res[off1]);
                v0 += q0.x; v1 += q0.y; v2 += q1.x; v3 += q1.y;
            }
            if (RELU) {
                v0 = fmaxf(v0, 0.f); v1 = fmaxf(v1, 0.f);
                v2 = fmaxf(v2, 0.f); v3 = fmaxf(v3, 0.f);
            }
            store2(&C[off0], v0, v1);
            store2(&C[off1], v2, v3);
        }
    }
}

template <typename TOut, bool RELU, bool RES>
__global__ __launch_bounds__(256, 1) void gemm_h_kernel(
    const __half* __restrict__ A, const __half* __restrict__ BT,
    const float* __restrict__ bias, const float* __restrict__ res,
    TOut* __restrict__ C, int M, int N, int K)
{
    gemm_h_body<TOut, RELU, RES>(A, BT, bias, res, C, M, N, K,
                                 blockIdx.x, blockIdx.y);
}

__global__ __launch_bounds__(256, 1) void gemm_h_qkv_kernel(
    const __half* __restrict__ A,
    const __half* __restrict__ wt0, const __half* __restrict__ wt1,
    const __half* __restrict__ wt2,
    const float* __restrict__ b0, const float* __restrict__ b1,
    const float* __restrict__ b2,
    __half* __restrict__ c0, __half* __restrict__ c1, __half* __restrict__ c2)
{
    const int z = blockIdx.z;
    const __half* BT  = (z == 0) ? wt0 : (z == 1) ? wt1 : wt2;
    const float* bias = (z == 0) ? b0  : (z == 1) ? b1  : b2;
    __half* C         = (z == 0) ? c0  : (z == 1) ? c1  : c2;
    gemm_h_body<__half, false, false>(A, BT, bias, nullptr, C,
                                      MROWS, EMB, EMB, blockIdx.x, blockIdx.y);
}

// ---------------- flash attention (fp16 m16n8k16) ---------------------------
#define AP 72

__global__ __launch_bounds__(128) void attn_h_kernel(
    const __half* __restrict__ q, const __half* __restrict__ k,
    const __half* __restrict__ v, __half* __restrict__ out)
{
    __shared__ __half Ks[64 * AP];
    __shared__ __half Vs[64 * AP];
    __shared__ __half Ps[64 * AP];

    const int qt = blockIdx.x, h = blockIdx.y, n = blockIdx.z;
    const int tid = threadIdx.x;
    const int warp = tid >> 5, lane = tid & 31;
    const int g = lane >> 2, t = lane & 3;
    const int w16 = warp * 16;
    const size_t base = ((size_t)n * SEQ) * EMB + h * HD;

    const uint32_t ksB = s2u(Ks), vsB = s2u(Vs), psB = s2u(Ps);

#pragma unroll
    for (int it = 0; it < 4; it++) {
        const int u = tid + it * 128;
        const int rr = u >> 3, c8 = (u & 7) * 8;
        *reinterpret_cast<uint4*>(&Ks[rr * AP + c8]) =
            *reinterpret_cast<const uint4*>(
                &q[base + (size_t)(qt * 64 + rr) * EMB + c8]);
    }
    __syncthreads();

    uint32_t qf[4][4];
#pragma unroll
    for (int ks = 0; ks < 4; ks++)
        ldm_x4(qf[ks], ksB + (uint32_t)(((w16 + (lane & 15)) * AP +
                                         ks * 16 + ((lane >> 4) * 8)) * 2));

    float m0 = -INFINITY, m1 = -INFINITY, l0 = 0.f, l1 = 0.f;
    float o[8][4];
#pragma unroll
    for (int nt = 0; nt < 8; nt++)
#pragma unroll
        for (int r = 0; r < 4; r++) o[nt][r] = 0.f;

    for (int kt = 0; kt < SEQ / 64; kt++) {
        __syncthreads();
#pragma unroll
        for (int it = 0; it < 4; it++) {
            const int u = tid + it * 128;
            const int rr = u >> 3, c8 = (u & 7) * 8;
            const size_t gsrc = base + (size_t)(kt * 64 + rr) * EMB + c8;
            *reinterpret_cast<uint4*>(&Ks[rr * AP + c8]) =
                *reinterpret_cast<const uint4*>(&k[gsrc]);
            *reinterpret_cast<uint4*>(&Vs[rr * AP + c8]) =
                *reinterpret_cast<const uint4*>(&v[gsrc]);
        }
        __syncthreads();

        float s[8][4];
#pragma unroll
        for (int nt = 0; nt < 8; nt++)
#pragma unroll
            for (int r = 0; r < 4; r++) s[nt][r] = 0.f;

#pragma unroll
        for (int ks = 0; ks < 4; ks++) {
#pragma unroll
            for (int j = 0; j < 4; j++) {
                uint32_t bf[4];
                ldm_x4(bf, ksB + (uint32_t)(((j * 16 + ((lane >> 4) << 3) +
                                              (lane & 7)) * AP + ks * 16 +
                                             ((lane >> 3) & 1) * 8) * 2));
                mma_f16(s[2 * j],     qf[ks], bf[0], bf[1]);
                mma_f16(s[2 * j + 1], qf[ks], bf[2], bf[3]);
            }
        }

#pragma unroll
        for (int nt = 0; nt < 8; nt++)
#pragma unroll
            for (int r = 0; r < 4; r++) s[nt][r] *= 0.125f;

        float mt0 = -INFINITY, mt1 = -INFINITY;
#pragma unroll
        for (int nt = 0; nt < 8; nt++) {
            mt0 = fmaxf(mt0, fmaxf(s[nt][0], s[nt][1]));
            mt1 = fmaxf(mt1, fmaxf(s[nt][2], s[nt][3]));
        }
        mt0 = fmaxf(mt0, __shfl_xor_sync(0xffffffffu, mt0, 1));
        mt0 = fmaxf(mt0, __shfl_xor_sync(0xffffffffu, mt0, 2));
        mt1 = fmaxf(mt1, __shfl_xor_sync(0xffffffffu, mt1, 1));
        mt1 = fmaxf(mt1, __shfl_xor_sync(0xffffffffu, mt1, 2));

        const float mn0 = fmaxf(m0, mt0), mn1 = fmaxf(m1, mt1);
        const float c0 = __expf(m0 - mn0), c1 = __expf(m1 - mn1);
        float ls0 = 0.f, ls1 = 0.f;
#pragma unroll
        for (int nt = 0; nt < 8; nt++) {
            const float p0 = __expf(s[nt][0] - mn0);
            const float p1 = __expf(s[nt][1] - mn0);
            const float p2 = __expf(s[nt][2] - mn1);
            const float p3 = __expf(s[nt][3] - mn1);
            ls0 += p0 + p1; ls1 += p2 + p3;
            *reinterpret_cast<uint32_t*>(
                &Ps[(w16 + g) * AP + nt * 8 + t * 2]) = pack_h2(p0, p1);
            *reinterpret_cast<uint32_t*>(
                &Ps[(w16 + g + 8) * AP + nt * 8 + t * 2]) = pack_h2(p2, p3);
        }
        ls0 += __shfl_xor_sync(0xffffffffu, ls0, 1);
        ls0 += __shfl_xor_sync(0xffffffffu, ls0, 2);
        ls1 += __shfl_xor_sync(0xffffffffu, ls1, 1);
        ls1 += __shfl_xor_sync(0xffffffffu, ls1, 2);
        l0 = l0 * c0 + ls0; l1 = l1 * c1 + ls1;
        m0 = mn0; m1 = mn1;
#pragma unroll
        for (int nt = 0; nt < 8; nt++) {
            o[nt][0] *= c0; o[nt][1] *= c0;
            o[nt][2] *= c1; o[nt][3] *= c1;
        }
        __syncwarp();

#pragma unroll
        for (int ks = 0; ks < 4; ks++) {
            uint32_t pf[4];
            ldm_x4(pf, psB + (uint32_t)(((w16 + (lane & 15)) * AP + ks * 16 +
                                         ((lane >> 4) * 8)) * 2));
#pragma unroll
            for (int j = 0; j < 4; j++) {
                uint32_t vf[4];
                const int row = ks * 16 + (lane & 7) + ((lane >> 3) & 1) * 8;
                ldm_x4_t(vf, vsB + (uint32_t)((row * AP + j * 16 +
                                               (lane >> 4) * 8) * 2));
                mma_f16(o[2 * j],     pf, vf[0], vf[1]);
                mma_f16(o[2 * j + 1], pf, vf[2], vf[3]);
            }
        }
    }

    const float i0 = 1.f / l0, i1 = 1.f / l1;
    const size_t row0 = base + (size_t)(qt * 64 + w16 + g) * EMB;
    const size_t row1 = base + (size_t)(qt * 64 + w16 + g + 8) * EMB;
#pragma unroll
    for (int nt = 0; nt < 8; nt++) {
        const int c = nt * 8 + t * 2;
        *reinterpret_cast<uint32_t*>(&out[row0 + c]) =
            pack_h2(o[nt][0] * i0, o[nt][1] * i0);
        *reinterpret_cast<uint32_t*>(&out[row1 + c]) =
            pack_h2(o[nt][2] * i1, o[nt][3] * i1);
    }
}

// ---------------- logits + GAN loss -----------------------------------------
__global__ void loss_kernel(const float* __restrict__ xfin,
                            const float* __restrict__ wlr,
                            const float* __restrict__ blr,
                            float* __restrict__ out)
{
    __shared__ float slog[4];
    const int warp = threadIdx.x >> 5, lane = threadIdx.x & 31;
    if (warp < 4) {
        const float* xr = xfin + (size_t)warp * SEQ * EMB;  // token 0
        float s = 0.f;
        for (int i = lane; i < EMB; i += 32) s = fmaf(xr[i], wlr[i], s);
#pragma unroll
        for (int off = 16; off; off >>= 1)
            s += __shfl_xor_sync(0xffffffffu, s, off);
        if (lane == 0) slog[warp] = s + blr[0];
    }
    __syncthreads();
    if (threadIdx.x == 0) {
        auto sp = [](float t) {
            return fmaxf(t, 0.f) + log1pf(expf(-fabsf(t)));
        };
        float loss_real = 0.5f * (sp(-slog[0]) + sp(-slog[1]));
        float loss_fake = 0.5f * (sp( slog[2]) + sp( slog[3]));
        out[0] = 0.5f * (loss_fake + loss_real);
        out[1] = loss_fake;
    }
}

// ---------------- launch ----------------------------------------------------
extern "C" void kernel_launch(void* const* d_in, const int* in_sizes, int n_in,
                              void* d_out, int out_size)
{
    const float* x     = (const float*)d_in[0];
    const float* wq    = (const float*)d_in[1];
    const float* bq    = (const float*)d_in[2];
    const float* wk    = (const float*)d_in[3];
    const float* bk    = (const float*)d_in[4];
    const float* wv    = (const float*)d_in[5];
    const float* bv    = (const float*)d_in[6];
    const float* wo    = (const float*)d_in[7];
    const float* bo    = (const float*)d_in[8];
    const float* ln1_g = (const float*)d_in[9];
    const float* ln1_b = (const float*)d_in[10];
    const float* ln2_g = (const float*)d_in[11];
    const float* ln2_b = (const float*)d_in[12];
    const float* w1    = (const float*)d_in[13];
    const float* b1    = (const float*)d_in[14];
    const float* w2    = (const float*)d_in[15];
    const float* b2    = (const float*)d_in[16];
    const float* wlr   = (const float*)d_in[17];
    const float* blr   = (const float*)d_in[18];
    float* out = (float*)d_out;

    __half *xn, *qh, *kh, *vh, *att, *xn2, *ffn;
    float* x1;
    __half *wtq, *wtk, *wtv, *wto, *wt1, *wt2;
    cudaGetSymbolAddress((void**)&xn,  g_xn);
    cudaGetSymbolAddress((void**)&qh,  g_q);
    cudaGetSymbolAddress((void**)&kh,  g_k);
    cudaGetSymbolAddress((void**)&vh,  g_v);
    cudaGetSymbolAddress((void**)&att, g_att);
    cudaGetSymbolAddress((void**)&x1,  g_x1);
    cudaGetSymbolAddress((void**)&xn2, g_xn2);
    cudaGetSymbolAddress((void**)&ffn, g_ffn);
    cudaGetSymbolAddress((void**)&wtq, g_wtq);
    cudaGetSymbolAddress((void**)&wtk, g_wtk);
    cudaGetSymbolAddress((void**)&wtv, g_wtv);
    cudaGetSymbolAddress((void**)&wto, g_wto);
    cudaGetSymbolAddress((void**)&wt1, g_wt1);
    cudaGetSymbolAddress((void**)&wt2, g_wt2);

    // raise dynamic smem limits
    cudaFuncSetAttribute(gemm_h_kernel<float, false, true>,
                         cudaFuncAttributeMaxDynamicSharedMemorySize, GEMM_DSMEM);
    cudaFuncSetAttribute(gemm_h_kernel<__half, true, false>,
                         cudaFuncAttributeMaxDynamicSharedMemorySize, GEMM_DSMEM);
    cudaFuncSetAttribute(gemm_h_qkv_kernel,
                         cudaFuncAttributeMaxDynamicSharedMemorySize, GEMM_DSMEM);

    // 0) weight transposes + fp16 convert
    dim3 tb(32, 8);
    transpose4_h_kernel<<<dim3(EMB / 32, EMB / 32, 4), tb>>>(
        wq, wk, wv, wo, wtq, wtk, wtv, wto);
    transpose_h_kernel<<<dim3(FF / 32,  EMB / 32), tb>>>(w1, wt1, EMB, FF);
    transpose_h_kernel<<<dim3(EMB / 32, FF / 32),  tb>>>(w2, wt2, FF, EMB);

    // 1) LN1 -> fp16
    ln_kernel<<<MROWS, 256>>>(x, ln1_g, ln1_b, xn);

    // 2) QKV projections -> fp16 q,k,v
    dim3 gQKV(EMB / 128, MROWS / 256, 3);
    gemm_h_qkv_kernel<<<gQKV, 256, GEMM_DSMEM>>>(xn, wtq, wtk, wtv,
                                                 bq, bk, bv, qh, kh, vh);

    // 3) attention (fp16 mma) -> fp16 att
    dim3 gAttn(SEQ / 64, NH, NB);
    attn_h_kernel<<<gAttn, 128>>>(qh, kh, vh, att);

    // 4) out-proj + residual(x fp32) -> x1 fp32
    dim3 gProj(EMB / 128, MROWS / 256);
    gemm_h_kernel<float, false, true><<<gProj, 256, GEMM_DSMEM>>>(
        att, wto, bo, x, x1, MROWS, EMB, EMB);

    // 5) LN2 -> fp16
    ln_kernel<<<MROWS, 256>>>(x1, ln2_g, ln2_b, xn2);

    // 6) FFN1 + ReLU -> fp16 ffn
    dim3 gFF1(FF / 128, MROWS / 256);
    gemm_h_kernel<__half, true, false><<<gFF1, 256, GEMM_DSMEM>>>(
        xn2, wt1, b1, nullptr, ffn, MROWS, FF, EMB);

    // 7) FFN2 + residual(x1 fp32) -> final fp32 out
    gemm_h_kernel<float, false, true><<<gProj, 256, GEMM_DSMEM>>>(
        ffn, wt2, b2, x1, out, MROWS, EMB, FF);

    // 8) logits + losses
    loss_kernel<<<1, 128>>>(out, wlr, blr, out + X_SIZE);
}